// round 2
// baseline (speedup 1.0000x reference)
#include <cuda_runtime.h>
#include <cuda_bf16.h>
#include <math.h>

// Problem constants (fixed by the dataset)
#define NN       50000
#define EE       800000
#define ETOT     (EE + NN)      // edges + self loops
#define FDIM     128            // all layer widths are 128 (H=2 heads x 64)

// ---------------- scratch (no allocations allowed) ----------------
__device__ float g_bufA[(size_t)NN * FDIM];
__device__ float g_bufB[(size_t)NN * FDIM];
__device__ float g_es[NN * 2];
__device__ float g_ed[NN * 2];
__device__ int   g_rowptr[NN + 1];
__device__ int   g_wp[NN];          // doubles as histogram counts, then write cursors
__device__ int   g_col[ETOT];       // src node id per CSR slot (grouped by dst)

// ---------------- CSR build ----------------
__global__ void zero_counts_kernel(int n) {
    int i = blockIdx.x * blockDim.x + threadIdx.x;
    if (i < n) g_wp[i] = 0;
}

__global__ void hist_kernel(const int* __restrict__ ei, int E, int n) {
    int e = blockIdx.x * blockDim.x + threadIdx.x;
    int etot = E + n;
    if (e >= etot) return;
    int d = (e < E) ? ei[E + e] : (e - E);
    atomicAdd(&g_wp[d], 1);
}

__global__ void scan_kernel(int n) {
    __shared__ int sh[1024];
    __shared__ int carry;
    if (threadIdx.x == 0) carry = 0;
    __syncthreads();
    for (int base = 0; base < n; base += 1024) {
        int i = base + threadIdx.x;
        int v = (i < n) ? g_wp[i] : 0;
        sh[threadIdx.x] = v;
        __syncthreads();
        for (int off = 1; off < 1024; off <<= 1) {
            int t = (threadIdx.x >= off) ? sh[threadIdx.x - off] : 0;
            __syncthreads();
            sh[threadIdx.x] += t;
            __syncthreads();
        }
        if (i < n) g_rowptr[i] = carry + sh[threadIdx.x] - v;   // exclusive
        __syncthreads();
        if (threadIdx.x == 1023) carry += sh[1023];
        __syncthreads();
    }
    if (threadIdx.x == 0) g_rowptr[n] = carry;
}

__global__ void init_wp_kernel(int n) {
    int i = blockIdx.x * blockDim.x + threadIdx.x;
    if (i < n) g_wp[i] = g_rowptr[i];
}

__global__ void scatter_kernel(const int* __restrict__ ei, int E, int n) {
    int e = blockIdx.x * blockDim.x + threadIdx.x;
    int etot = E + n;
    if (e >= etot) return;
    int s, d;
    if (e < E) { s = ei[e]; d = ei[E + e]; }
    else       { s = e - E; d = s; }
    int p = atomicAdd(&g_wp[d], 1);
    g_col[p] = s;
}

// ---------------- SGEMM: C[M,128] = A[M,128] @ W[128,128] ----------------
// BM=128, BN=128, BK=16; 256 threads, 8x8 micro-tile per thread.
__global__ __launch_bounds__(256) void sgemm128_kernel(
    const float* __restrict__ A, const float* __restrict__ W,
    float* __restrict__ C, int M)
{
    __shared__ float As[16][132];   // transposed A tile, padded
    __shared__ float Bs[16][132];
    int block_row = blockIdx.x * 128;
    int tid = threadIdx.x;
    int tr = tid >> 4;       // 0..15
    int tc = tid & 15;       // 0..15
    float acc[8][8];
#pragma unroll
    for (int i = 0; i < 8; i++)
#pragma unroll
        for (int j = 0; j < 8; j++) acc[i][j] = 0.f;

    for (int k0 = 0; k0 < 128; k0 += 16) {
        // load A tile: 128 rows x 16 cols = 512 float4s
#pragma unroll
        for (int l = 0; l < 2; l++) {
            int f = tid + l * 256;
            int r = f >> 2;
            int c4 = (f & 3) * 4;
            int gr = block_row + r;
            float4 v = make_float4(0.f, 0.f, 0.f, 0.f);
            if (gr < M) v = *reinterpret_cast<const float4*>(&A[(size_t)gr * 128 + k0 + c4]);
            As[c4 + 0][r] = v.x;
            As[c4 + 1][r] = v.y;
            As[c4 + 2][r] = v.z;
            As[c4 + 3][r] = v.w;
        }
        // load B tile: 16 rows x 128 cols
#pragma unroll
        for (int l = 0; l < 2; l++) {
            int f = tid + l * 256;
            int r = f >> 5;
            int c4 = (f & 31) * 4;
            float4 v = *reinterpret_cast<const float4*>(&W[(size_t)(k0 + r) * 128 + c4]);
            *reinterpret_cast<float4*>(&Bs[r][c4]) = v;
        }
        __syncthreads();
#pragma unroll
        for (int k = 0; k < 16; k++) {
            float a[8], b[8];
            float4 a0 = *reinterpret_cast<const float4*>(&As[k][tr * 8]);
            float4 a1 = *reinterpret_cast<const float4*>(&As[k][tr * 8 + 4]);
            float4 b0 = *reinterpret_cast<const float4*>(&Bs[k][tc * 8]);
            float4 b1 = *reinterpret_cast<const float4*>(&Bs[k][tc * 8 + 4]);
            a[0]=a0.x;a[1]=a0.y;a[2]=a0.z;a[3]=a0.w;a[4]=a1.x;a[5]=a1.y;a[6]=a1.z;a[7]=a1.w;
            b[0]=b0.x;b[1]=b0.y;b[2]=b0.z;b[3]=b0.w;b[4]=b1.x;b[5]=b1.y;b[6]=b1.z;b[7]=b1.w;
#pragma unroll
            for (int i = 0; i < 8; i++)
#pragma unroll
                for (int j = 0; j < 8; j++)
                    acc[i][j] += a[i] * b[j];
        }
        __syncthreads();
    }
    // store
#pragma unroll
    for (int i = 0; i < 8; i++) {
        int gr = block_row + tr * 8 + i;
        if (gr < M) {
            float4 v0 = make_float4(acc[i][0], acc[i][1], acc[i][2], acc[i][3]);
            float4 v1 = make_float4(acc[i][4], acc[i][5], acc[i][6], acc[i][7]);
            *reinterpret_cast<float4*>(&C[(size_t)gr * 128 + tc * 8])     = v0;
            *reinterpret_cast<float4*>(&C[(size_t)gr * 128 + tc * 8 + 4]) = v1;
        }
    }
}

// ---------------- per-node attention coefficients ----------------
// e_src[n,h] = sum_c h[n, h*64+c] * a_src[h*64+c]   (a_* flattened [128])
__global__ void e_kernel(const float* __restrict__ h,
                         const float* __restrict__ av_src,
                         const float* __restrict__ av_dst, int n)
{
    int w = (blockIdx.x * blockDim.x + threadIdx.x) >> 5;
    int lane = threadIdx.x & 31;
    if (w >= n) return;
    const float* hr = h + (size_t)w * 128;
    float h0 = hr[lane], h1 = hr[lane + 32], h2 = hr[lane + 64], h3 = hr[lane + 96];
    float s0 = h0 * av_src[lane]      + h1 * av_src[lane + 32];
    float s1 = h2 * av_src[lane + 64] + h3 * av_src[lane + 96];
    float d0 = h0 * av_dst[lane]      + h1 * av_dst[lane + 32];
    float d1 = h2 * av_dst[lane + 64] + h3 * av_dst[lane + 96];
#pragma unroll
    for (int o = 16; o; o >>= 1) {
        s0 += __shfl_xor_sync(0xffffffffu, s0, o);
        s1 += __shfl_xor_sync(0xffffffffu, s1, o);
        d0 += __shfl_xor_sync(0xffffffffu, d0, o);
        d1 += __shfl_xor_sync(0xffffffffu, d1, o);
    }
    if (lane == 0) {
        g_es[2 * w] = s0; g_es[2 * w + 1] = s1;
        g_ed[2 * w] = d0; g_ed[2 * w + 1] = d1;
    }
}

__device__ __forceinline__ float lrelu(float x) { return x > 0.f ? x : 0.2f * x; }

// ---------------- fused softmax-aggregate (warp per dst node) ----------------
__global__ void agg_kernel(const float* __restrict__ h,
                           const float* __restrict__ bias,
                           float* __restrict__ out, int n)
{
    int w = (blockIdx.x * blockDim.x + threadIdx.x) >> 5;
    int lane = threadIdx.x & 31;
    if (w >= n) return;
    int start = g_rowptr[w], end = g_rowptr[w + 1];
    float ed0 = g_ed[2 * w], ed1 = g_ed[2 * w + 1];

    // pass 1: per-head max over incoming edges
    float m0 = -3.0e38f, m1 = -3.0e38f;
    for (int j = start + lane; j < end; j += 32) {
        int s = g_col[j];
        m0 = fmaxf(m0, lrelu(g_es[2 * s]     + ed0));
        m1 = fmaxf(m1, lrelu(g_es[2 * s + 1] + ed1));
    }
#pragma unroll
    for (int o = 16; o; o >>= 1) {
        m0 = fmaxf(m0, __shfl_xor_sync(0xffffffffu, m0, o));
        m1 = fmaxf(m1, __shfl_xor_sync(0xffffffffu, m1, o));
    }

    // pass 2: accumulate exp-weighted features; lane covers cols 4*lane..4*lane+3
    float acc0 = 0.f, acc1 = 0.f, acc2 = 0.f, acc3 = 0.f;
    float den0 = 0.f, den1 = 0.f;
    const float4* h4 = reinterpret_cast<const float4*>(h);
    bool head0 = (lane < 16);
    for (int j = start; j < end; j++) {
        int s = g_col[j];
        float w0 = __expf(lrelu(g_es[2 * s]     + ed0) - m0);
        float w1 = __expf(lrelu(g_es[2 * s + 1] + ed1) - m1);
        den0 += w0; den1 += w1;
        float wgt = head0 ? w0 : w1;
        float4 hv = h4[(size_t)s * 32 + lane];
        acc0 += wgt * hv.x; acc1 += wgt * hv.y;
        acc2 += wgt * hv.z; acc3 += wgt * hv.w;
    }
    float inv = 1.0f / (head0 ? den0 : den1);
    float4 bb = reinterpret_cast<const float4*>(bias)[lane];
    float o0 = acc0 * inv + bb.x;
    float o1 = acc1 * inv + bb.y;
    float o2 = acc2 * inv + bb.z;
    float o3 = acc3 * inv + bb.w;
    // ELU (alpha=1), expm1 for accuracy near 0-
    o0 = o0 > 0.f ? o0 : expm1f(o0);
    o1 = o1 > 0.f ? o1 : expm1f(o1);
    o2 = o2 > 0.f ? o2 : expm1f(o2);
    o3 = o3 > 0.f ? o3 : expm1f(o3);
    reinterpret_cast<float4*>(out)[(size_t)w * 32 + lane] = make_float4(o0, o1, o2, o3);
}

// ---------------- host ----------------
extern "C" void kernel_launch(void* const* d_in, const int* in_sizes, int n_in,
                              void* d_out, int out_size)
{
    const float* x   = (const float*)d_in[0];
    const int*   ei  = (const int*)d_in[1];     // edge_index is int32 on device (JAX x64 off)
    const float* W1  = (const float*)d_in[2];
    const float* as1 = (const float*)d_in[3];
    const float* ad1 = (const float*)d_in[4];
    const float* b1  = (const float*)d_in[5];
    const float* W2  = (const float*)d_in[6];
    const float* as2 = (const float*)d_in[7];
    const float* ad2 = (const float*)d_in[8];
    const float* b2  = (const float*)d_in[9];
    const float* W3  = (const float*)d_in[10];
    const float* as3 = (const float*)d_in[11];
    const float* ad3 = (const float*)d_in[12];
    const float* b3  = (const float*)d_in[13];
    float*       out = (float*)d_out;

    int n = in_sizes[0] / FDIM;          // 50000
    int E = in_sizes[1] / 2;             // 800000

    void* pA; cudaGetSymbolAddress(&pA, g_bufA);
    void* pB; cudaGetSymbolAddress(&pB, g_bufB);
    float* bufA = (float*)pA;
    float* bufB = (float*)pB;

    int nblkNodes = (n + 255) / 256;
    int nblkEdges = (E + n + 255) / 256;
    int nblkWarp  = (n * 32 + 255) / 256;
    int nblkGemm  = (n + 127) / 128;

    // CSR build (by dst)
    zero_counts_kernel<<<nblkNodes, 256>>>(n);
    hist_kernel<<<nblkEdges, 256>>>(ei, E, n);
    scan_kernel<<<1, 1024>>>(n);
    init_wp_kernel<<<nblkNodes, 256>>>(n);
    scatter_kernel<<<nblkEdges, 256>>>(ei, E, n);

    // layer 1
    sgemm128_kernel<<<nblkGemm, 256>>>(x, W1, bufA, n);
    e_kernel<<<nblkWarp, 256>>>(bufA, as1, ad1, n);
    agg_kernel<<<nblkWarp, 256>>>(bufA, b1, bufB, n);
    // layer 2
    sgemm128_kernel<<<nblkGemm, 256>>>(bufB, W2, bufA, n);
    e_kernel<<<nblkWarp, 256>>>(bufA, as2, ad2, n);
    agg_kernel<<<nblkWarp, 256>>>(bufA, b2, bufB, n);
    // layer 3
    sgemm128_kernel<<<nblkGemm, 256>>>(bufB, W3, bufA, n);
    e_kernel<<<nblkWarp, 256>>>(bufA, as3, ad3, n);
    agg_kernel<<<nblkWarp, 256>>>(bufA, b3, out, n);
}

// round 3
// speedup vs baseline: 1.1113x; 1.1113x over previous
#include <cuda_runtime.h>
#include <cuda_bf16.h>
#include <math.h>

// Problem constants (fixed by the dataset)
#define NN       50000
#define EE       800000
#define ETOT     (EE + NN)      // edges + self loops
#define FDIM     128            // all layer widths are 128 (H=2 heads x 64)

// ---------------- scratch (no allocations allowed) ----------------
__device__ float g_bufA[(size_t)NN * FDIM];
__device__ float g_bufB[(size_t)NN * FDIM];
__device__ float g_es[NN * 2];      // interleaved [node][head]
__device__ float g_ed[NN * 2];
__device__ int   g_rowptr[NN + 1];
__device__ int   g_wp[NN];          // histogram counts, then write cursors
__device__ int   g_col[ETOT];       // src node id per CSR slot (grouped by dst)

// ---------------- CSR build ----------------
__global__ void zero_counts_kernel(int n) {
    int i = blockIdx.x * blockDim.x + threadIdx.x;
    if (i < n) g_wp[i] = 0;
}

__global__ void hist_kernel(const int* __restrict__ ei, int E, int n) {
    int e = blockIdx.x * blockDim.x + threadIdx.x;
    int etot = E + n;
    if (e >= etot) return;
    int d = (e < E) ? ei[E + e] : (e - E);
    atomicAdd(&g_wp[d], 1);
}

// Shuffle-based single-block scan, 4096 elements per outer iteration.
// Writes exclusive prefix into BOTH g_rowptr and g_wp (write cursors).
__global__ __launch_bounds__(1024) void scan_kernel(int n) {
    __shared__ int wsum[32];
    __shared__ int carry_sh;
    int lane = threadIdx.x & 31, wid = threadIdx.x >> 5;
    if (threadIdx.x == 0) carry_sh = 0;
    __syncthreads();
    for (int base = 0; base < n; base += 4096) {
        int idx = base + threadIdx.x * 4;
        int v0 = (idx + 0 < n) ? g_wp[idx + 0] : 0;
        int v1 = (idx + 1 < n) ? g_wp[idx + 1] : 0;
        int v2 = (idx + 2 < n) ? g_wp[idx + 2] : 0;
        int v3 = (idx + 3 < n) ? g_wp[idx + 3] : 0;
        int tsum = v0 + v1 + v2 + v3;
        int x = tsum;
#pragma unroll
        for (int off = 1; off < 32; off <<= 1) {
            int y = __shfl_up_sync(0xffffffffu, x, off);
            if (lane >= off) x += y;
        }
        if (lane == 31) wsum[wid] = x;
        __syncthreads();
        if (wid == 0) {
            int ws = wsum[lane];
#pragma unroll
            for (int off = 1; off < 32; off <<= 1) {
                int y = __shfl_up_sync(0xffffffffu, ws, off);
                if (lane >= off) ws += y;
            }
            wsum[lane] = ws;
        }
        __syncthreads();
        int carry = carry_sh;
        int excl = carry + (wid ? wsum[wid - 1] : 0) + (x - tsum);
        if (idx + 0 < n) { g_rowptr[idx + 0] = excl; g_wp[idx + 0] = excl; } excl += v0;
        if (idx + 1 < n) { g_rowptr[idx + 1] = excl; g_wp[idx + 1] = excl; } excl += v1;
        if (idx + 2 < n) { g_rowptr[idx + 2] = excl; g_wp[idx + 2] = excl; } excl += v2;
        if (idx + 3 < n) { g_rowptr[idx + 3] = excl; g_wp[idx + 3] = excl; }
        int total = wsum[31];
        __syncthreads();
        if (threadIdx.x == 0) carry_sh = carry + total;
        __syncthreads();
    }
    if (threadIdx.x == 0) g_rowptr[n] = carry_sh;
}

__global__ void scatter_kernel(const int* __restrict__ ei, int E, int n) {
    int e = blockIdx.x * blockDim.x + threadIdx.x;
    int etot = E + n;
    if (e >= etot) return;
    int s, d;
    if (e < E) { s = ei[e]; d = ei[E + e]; }
    else       { s = e - E; d = s; }
    int p = atomicAdd(&g_wp[d], 1);
    g_col[p] = s;
}

// ---------------- SGEMM + fused attention-coefficient epilogue ----------------
// C[M,128] = A[M,128] @ W[128,128]; also es/ed[row][head] = <C_row_head, a_*>.
// BM=128, BN=128, BK=16; 256 threads, 8x8 micro-tile per thread.
__global__ __launch_bounds__(256) void sgemm128_kernel(
    const float* __restrict__ A, const float* __restrict__ W,
    const float* __restrict__ av_src, const float* __restrict__ av_dst,
    float* __restrict__ C, int M)
{
    __shared__ float As[16][132];   // transposed A tile, padded
    __shared__ float Bs[16][132];
    int block_row = blockIdx.x * 128;
    int tid = threadIdx.x;
    int tr = tid >> 4;       // 0..15 (row group)
    int tc = tid & 15;       // 0..15 (col group)
    float acc[8][8];
#pragma unroll
    for (int i = 0; i < 8; i++)
#pragma unroll
        for (int j = 0; j < 8; j++) acc[i][j] = 0.f;

    for (int k0 = 0; k0 < 128; k0 += 16) {
#pragma unroll
        for (int l = 0; l < 2; l++) {
            int f = tid + l * 256;
            int r = f >> 2;
            int c4 = (f & 3) * 4;
            int gr = block_row + r;
            float4 v = make_float4(0.f, 0.f, 0.f, 0.f);
            if (gr < M) v = *reinterpret_cast<const float4*>(&A[(size_t)gr * 128 + k0 + c4]);
            As[c4 + 0][r] = v.x;
            As[c4 + 1][r] = v.y;
            As[c4 + 2][r] = v.z;
            As[c4 + 3][r] = v.w;
        }
#pragma unroll
        for (int l = 0; l < 2; l++) {
            int f = tid + l * 256;
            int r = f >> 5;
            int c4 = (f & 31) * 4;
            float4 v = *reinterpret_cast<const float4*>(&W[(size_t)(k0 + r) * 128 + c4]);
            *reinterpret_cast<float4*>(&Bs[r][c4]) = v;
        }
        __syncthreads();
#pragma unroll
        for (int k = 0; k < 16; k++) {
            float a[8], b[8];
            float4 a0 = *reinterpret_cast<const float4*>(&As[k][tr * 8]);
            float4 a1 = *reinterpret_cast<const float4*>(&As[k][tr * 8 + 4]);
            float4 b0 = *reinterpret_cast<const float4*>(&Bs[k][tc * 8]);
            float4 b1 = *reinterpret_cast<const float4*>(&Bs[k][tc * 8 + 4]);
            a[0]=a0.x;a[1]=a0.y;a[2]=a0.z;a[3]=a0.w;a[4]=a1.x;a[5]=a1.y;a[6]=a1.z;a[7]=a1.w;
            b[0]=b0.x;b[1]=b0.y;b[2]=b0.z;b[3]=b0.w;b[4]=b1.x;b[5]=b1.y;b[6]=b1.z;b[7]=b1.w;
#pragma unroll
            for (int i = 0; i < 8; i++)
#pragma unroll
                for (int j = 0; j < 8; j++)
                    acc[i][j] += a[i] * b[j];
        }
        __syncthreads();
    }

    // store C
#pragma unroll
    for (int i = 0; i < 8; i++) {
        int gr = block_row + tr * 8 + i;
        if (gr < M) {
            float4 v0 = make_float4(acc[i][0], acc[i][1], acc[i][2], acc[i][3]);
            float4 v1 = make_float4(acc[i][4], acc[i][5], acc[i][6], acc[i][7]);
            *reinterpret_cast<float4*>(&C[(size_t)gr * 128 + tc * 8])     = v0;
            *reinterpret_cast<float4*>(&C[(size_t)gr * 128 + tc * 8 + 4]) = v1;
        }
    }

    // fused e_src / e_dst epilogue.
    // Thread covers cols tc*8..tc*8+7 (one head: tc<8 -> head0, tc>=8 -> head1).
    float4 s0 = *reinterpret_cast<const float4*>(&av_src[tc * 8]);
    float4 s1 = *reinterpret_cast<const float4*>(&av_src[tc * 8 + 4]);
    float4 d0 = *reinterpret_cast<const float4*>(&av_dst[tc * 8]);
    float4 d1 = *reinterpret_cast<const float4*>(&av_dst[tc * 8 + 4]);
#pragma unroll
    for (int i = 0; i < 8; i++) {
        float ps = acc[i][0]*s0.x + acc[i][1]*s0.y + acc[i][2]*s0.z + acc[i][3]*s0.w
                 + acc[i][4]*s1.x + acc[i][5]*s1.y + acc[i][6]*s1.z + acc[i][7]*s1.w;
        float pd = acc[i][0]*d0.x + acc[i][1]*d0.y + acc[i][2]*d0.z + acc[i][3]*d0.w
                 + acc[i][4]*d1.x + acc[i][5]*d1.y + acc[i][6]*d1.z + acc[i][7]*d1.w;
#pragma unroll
        for (int off = 1; off < 8; off <<= 1) {
            ps += __shfl_xor_sync(0xffffffffu, ps, off);
            pd += __shfl_xor_sync(0xffffffffu, pd, off);
        }
        int row = block_row + tr * 8 + i;
        if (row < M) {
            if (tc == 0) { g_es[2 * row]     = ps; g_ed[2 * row]     = pd; }
            if (tc == 8) { g_es[2 * row + 1] = ps; g_ed[2 * row + 1] = pd; }
        }
    }
}

__device__ __forceinline__ float lrelu(float x) { return x > 0.f ? x : 0.2f * x; }

// ---------------- fused softmax-aggregate (warp per dst node) ----------------
// Chunked: 32 edges per chunk; lanes compute weights in parallel, then the
// per-edge feature gather loop gets (src, weight) via shfl — no pointer chase.
__global__ __launch_bounds__(256) void agg_kernel(
    const float* __restrict__ h, const float* __restrict__ bias,
    float* __restrict__ out, int n)
{
    int w = (blockIdx.x * blockDim.x + threadIdx.x) >> 5;
    int lane = threadIdx.x & 31;
    if (w >= n) return;
    int start = g_rowptr[w], end = g_rowptr[w + 1];
    const float2* es2 = reinterpret_cast<const float2*>(g_es);
    const float2* ed2 = reinterpret_cast<const float2*>(g_ed);
    float2 ed = ed2[w];

    // pass 1: per-head max over incoming edges (lane-parallel)
    float m0 = -3.0e38f, m1 = -3.0e38f;
    for (int j = start + lane; j < end; j += 32) {
        int s = g_col[j];
        float2 es = es2[s];
        m0 = fmaxf(m0, lrelu(es.x + ed.x));
        m1 = fmaxf(m1, lrelu(es.y + ed.y));
    }
#pragma unroll
    for (int o = 16; o; o >>= 1) {
        m0 = fmaxf(m0, __shfl_xor_sync(0xffffffffu, m0, o));
        m1 = fmaxf(m1, __shfl_xor_sync(0xffffffffu, m1, o));
    }

    // pass 2: chunked accumulate; lane covers cols 4*lane..4*lane+3
    float acc0 = 0.f, acc1 = 0.f, acc2 = 0.f, acc3 = 0.f;
    float den0 = 0.f, den1 = 0.f;
    const float4* h4 = reinterpret_cast<const float4*>(h);
    bool head0 = (lane < 16);
    for (int chunk = start; chunk < end; chunk += 32) {
        int j = chunk + lane;
        int s = 0; float w0 = 0.f, w1 = 0.f;
        if (j < end) {
            s = g_col[j];
            float2 es = es2[s];
            w0 = __expf(lrelu(es.x + ed.x) - m0);
            w1 = __expf(lrelu(es.y + ed.y) - m1);
        }
        den0 += w0; den1 += w1;
        int cnt = min(32, end - chunk);
#pragma unroll 4
        for (int k = 0; k < cnt; k++) {
            int   ss  = __shfl_sync(0xffffffffu, s,  k);
            float wk0 = __shfl_sync(0xffffffffu, w0, k);
            float wk1 = __shfl_sync(0xffffffffu, w1, k);
            float wk  = head0 ? wk0 : wk1;
            float4 hv = h4[(size_t)ss * 32 + lane];
            acc0 += wk * hv.x; acc1 += wk * hv.y;
            acc2 += wk * hv.z; acc3 += wk * hv.w;
        }
    }
#pragma unroll
    for (int o = 16; o; o >>= 1) {
        den0 += __shfl_xor_sync(0xffffffffu, den0, o);
        den1 += __shfl_xor_sync(0xffffffffu, den1, o);
    }
    float inv = 1.0f / (head0 ? den0 : den1);
    float4 bb = reinterpret_cast<const float4*>(bias)[lane];
    float o0 = acc0 * inv + bb.x;
    float o1 = acc1 * inv + bb.y;
    float o2 = acc2 * inv + bb.z;
    float o3 = acc3 * inv + bb.w;
    o0 = o0 > 0.f ? o0 : expm1f(o0);
    o1 = o1 > 0.f ? o1 : expm1f(o1);
    o2 = o2 > 0.f ? o2 : expm1f(o2);
    o3 = o3 > 0.f ? o3 : expm1f(o3);
    reinterpret_cast<float4*>(out)[(size_t)w * 32 + lane] = make_float4(o0, o1, o2, o3);
}

// ---------------- host ----------------
extern "C" void kernel_launch(void* const* d_in, const int* in_sizes, int n_in,
                              void* d_out, int out_size)
{
    const float* x   = (const float*)d_in[0];
    const int*   ei  = (const int*)d_in[1];     // edge_index is int32 on device
    const float* W1  = (const float*)d_in[2];
    const float* as1 = (const float*)d_in[3];
    const float* ad1 = (const float*)d_in[4];
    const float* b1  = (const float*)d_in[5];
    const float* W2  = (const float*)d_in[6];
    const float* as2 = (const float*)d_in[7];
    const float* ad2 = (const float*)d_in[8];
    const float* b2  = (const float*)d_in[9];
    const float* W3  = (const float*)d_in[10];
    const float* as3 = (const float*)d_in[11];
    const float* ad3 = (const float*)d_in[12];
    const float* b3  = (const float*)d_in[13];
    float*       out = (float*)d_out;

    int n = in_sizes[0] / FDIM;          // 50000
    int E = in_sizes[1] / 2;             // 800000

    void* pA; cudaGetSymbolAddress(&pA, g_bufA);
    void* pB; cudaGetSymbolAddress(&pB, g_bufB);
    float* bufA = (float*)pA;
    float* bufB = (float*)pB;

    int nblkNodes = (n + 255) / 256;
    int nblkEdges = (E + n + 255) / 256;
    int nblkWarp  = (n * 32 + 255) / 256;
    int nblkGemm  = (n + 127) / 128;

    // CSR build (by dst): 4 launches
    zero_counts_kernel<<<nblkNodes, 256>>>(n);
    hist_kernel<<<nblkEdges, 256>>>(ei, E, n);
    scan_kernel<<<1, 1024>>>(n);
    scatter_kernel<<<nblkEdges, 256>>>(ei, E, n);

    // layer 1  (launch 5 = sgemm, launch 6 = agg -> ncu -s 5 captures agg)
    sgemm128_kernel<<<nblkGemm, 256>>>(x, W1, as1, ad1, bufA, n);
    agg_kernel<<<nblkWarp, 256>>>(bufA, b1, bufB, n);
    // layer 2
    sgemm128_kernel<<<nblkGemm, 256>>>(bufB, W2, as2, ad2, bufA, n);
    agg_kernel<<<nblkWarp, 256>>>(bufA, b2, bufB, n);
    // layer 3
    sgemm128_kernel<<<nblkGemm, 256>>>(bufB, W3, as3, ad3, bufA, n);
    agg_kernel<<<nblkWarp, 256>>>(bufA, b3, out, n);
}